// round 1
// baseline (speedup 1.0000x reference)
#include <cuda_runtime.h>
#include <cuda_bf16.h>

// GATConv_74904229642448
//
// The reference's einsum 'bij,bjk->bkj' contracts ONLY over i, which appears
// only in the (row-normalized) attention tensor: sum_i alpha[b,i,h] == 1.
// The whole attention block is an exact multiply-by-one. The output is:
//   out[n, k*8 + h] = dot(x[n,:], W[h*64 + k, :]) + bias[k*8 + h]
// => a single 4096x512x256 fp32 GEMM with a permuted B operand. adj is unused.

#define N_NODES 4096
#define IN_C    256
#define OUT_TOT 512   // HEADS * OUT_C
#define BM 128
#define BN 128
#define BK 16
#define PAD 132       // padded smem row stride (16B-aligned: 132*4 = 528 = 33*16)

__global__ __launch_bounds__(256, 1)
void gat_gemm_kernel(const float* __restrict__ x,
                     const float* __restrict__ W,
                     const float* __restrict__ bias,
                     float* __restrict__ out)
{
    __shared__ float As[BK][PAD];   // As[k][m]
    __shared__ float Bs[BK][PAD];   // Bs[k][n]

    const int tid = threadIdx.x;
    const int m0 = blockIdx.y * BM;
    const int n0 = blockIdx.x * BN;

    // Global-load assignment: each thread owns one tile-row and half its BK=16
    // columns (2x float4).
    const int lrow = tid >> 1;          // 0..127
    const int lk   = (tid & 1) * 8;     // 0 or 8

    const float* Arow = x + (size_t)(m0 + lrow) * IN_C + lk;
    const int jcol = n0 + lrow;         // output column -> permuted W row
    const float* Brow = W + (size_t)((jcol & 7) * 64 + (jcol >> 3)) * IN_C + lk;

    // Compute assignment: 16x16 thread grid, 8x8 microtile each.
    const int tx = tid & 15;
    const int ty = tid >> 4;

    float acc[8][8];
    #pragma unroll
    for (int i = 0; i < 8; i++)
        #pragma unroll
        for (int j = 0; j < 8; j++)
            acc[i][j] = 0.f;

    for (int k0 = 0; k0 < IN_C; k0 += BK) {
        // Stage next tile in registers before the barrier.
        float4 a0 = *(const float4*)(Arow + k0);
        float4 a1 = *(const float4*)(Arow + k0 + 4);
        float4 b0 = *(const float4*)(Brow + k0);
        float4 b1 = *(const float4*)(Brow + k0 + 4);

        __syncthreads();   // previous tile's compute must finish before overwrite
        As[lk+0][lrow] = a0.x; As[lk+1][lrow] = a0.y;
        As[lk+2][lrow] = a0.z; As[lk+3][lrow] = a0.w;
        As[lk+4][lrow] = a1.x; As[lk+5][lrow] = a1.y;
        As[lk+6][lrow] = a1.z; As[lk+7][lrow] = a1.w;
        Bs[lk+0][lrow] = b0.x; Bs[lk+1][lrow] = b0.y;
        Bs[lk+2][lrow] = b0.z; Bs[lk+3][lrow] = b0.w;
        Bs[lk+4][lrow] = b1.x; Bs[lk+5][lrow] = b1.y;
        Bs[lk+6][lrow] = b1.z; Bs[lk+7][lrow] = b1.w;
        __syncthreads();

        #pragma unroll
        for (int k = 0; k < BK; k++) {
            float a[8], b[8];
            *(float4*)&a[0] = *(const float4*)&As[k][ty * 8];
            *(float4*)&a[4] = *(const float4*)&As[k][ty * 8 + 4];
            *(float4*)&b[0] = *(const float4*)&Bs[k][tx * 8];
            *(float4*)&b[4] = *(const float4*)&Bs[k][tx * 8 + 4];
            #pragma unroll
            for (int i = 0; i < 8; i++)
                #pragma unroll
                for (int j = 0; j < 8; j++)
                    acc[i][j] = fmaf(a[i], b[j], acc[i][j]);
        }
    }

    // Epilogue: add bias, vectorized store.
    float4 blo = *(const float4*)(bias + n0 + tx * 8);
    float4 bhi = *(const float4*)(bias + n0 + tx * 8 + 4);
    #pragma unroll
    for (int i = 0; i < 8; i++) {
        float4 o0 = make_float4(acc[i][0] + blo.x, acc[i][1] + blo.y,
                                acc[i][2] + blo.z, acc[i][3] + blo.w);
        float4 o1 = make_float4(acc[i][4] + bhi.x, acc[i][5] + bhi.y,
                                acc[i][6] + bhi.z, acc[i][7] + bhi.w);
        float* orow = out + (size_t)(m0 + ty * 8 + i) * OUT_TOT + n0 + tx * 8;
        *(float4*)(orow)     = o0;
        *(float4*)(orow + 4) = o1;
    }
}

extern "C" void kernel_launch(void* const* d_in, const int* in_sizes, int n_in,
                              void* d_out, int out_size) {
    // metadata order: adj, x, W, att_src, att_dst, bias
    const float* x    = (const float*)d_in[1];
    const float* W    = (const float*)d_in[2];
    const float* bias = (const float*)d_in[5];
    float* out        = (float*)d_out;

    dim3 grid(OUT_TOT / BN, N_NODES / BM);   // (4, 32) = 128 blocks
    gat_gemm_kernel<<<grid, 256>>>(x, W, bias, out);
}

// round 3
// speedup vs baseline: 1.6965x; 1.6965x over previous
#include <cuda_runtime.h>
#include <cuda_bf16.h>
#include <cstdint>

// GATConv_74904229642448 — the attention tensor is row-normalized and then
// contracted ONLY over its normalization axis (einsum 'bij,bjk->bkj' shares
// no index between alpha's i and xp except via the sum), so sum_i alpha == 1
// exactly. Output collapses to a permuted projection:
//   out[n, j] = dot(x[n,:], W[(j&7)*64 + (j>>3), :]) + bias[j]
// => 4096x512x256 fp32 GEMM. adj (64MB) is never read.
//
// tcgen05 is unreachable (harness PTX target is compute_103, not sm_103a),
// so we use classic mma.sync bf16 (sm_80+ PTX, runs on Blackwell HMMA pipe)
// with the split-bf16 3-term trick: x = hi + lo (both bf16),
//   D = Ah*Bh + Ah*Bl + Al*Bh   (fp32 accumulate)  ->  ~1e-5 rel error.

#define N_NODES 4096
#define IN_C    256
#define OUT_TOT 512
#define BM 128
#define BN 128
#define KC 32
#define NCHUNK (IN_C / KC)      // 8
#define PITCH 80                // smem row pitch bytes: 32 bf16 * 2B + 16 pad
#define REGION (128 * PITCH)    // 10240 B per tile region

static __device__ __forceinline__ uint32_t smem_u32(const void* p) {
    uint32_t a;
    asm("{ .reg .u64 t; cvta.to.shared.u64 t, %1; cvt.u32.u64 %0, t; }"
        : "=r"(a) : "l"(p));
    return a;
}

static __device__ __forceinline__ void cvt2(float a, float b, uint32_t& h, uint32_t& l) {
    __nv_bfloat16 ha = __float2bfloat16(a);
    __nv_bfloat16 hb = __float2bfloat16(b);
    float ra = a - __bfloat162float(ha);
    float rb = b - __bfloat162float(hb);
    __nv_bfloat16 la = __float2bfloat16(ra);
    __nv_bfloat16 lb = __float2bfloat16(rb);
    h = ((uint32_t)__bfloat16_as_ushort(hb) << 16) | (uint32_t)__bfloat16_as_ushort(ha);
    l = ((uint32_t)__bfloat16_as_ushort(lb) << 16) | (uint32_t)__bfloat16_as_ushort(la);
}

static __device__ __forceinline__ void st128(uint32_t addr, uint32_t a, uint32_t b,
                                             uint32_t c, uint32_t d) {
    asm volatile("st.shared.v4.b32 [%0], {%1,%2,%3,%4};"
                 :: "r"(addr), "r"(a), "r"(b), "r"(c), "r"(d) : "memory");
}

// Convert 8 fp32 -> 8 hi-bf16 + 8 lo-bf16, store 16B to each region.
static __device__ __forceinline__ void cvt_store8(float4 v0, float4 v1,
                                                  uint32_t hi_addr, uint32_t lo_addr) {
    uint32_t h0, h1, h2, h3, l0, l1, l2, l3;
    cvt2(v0.x, v0.y, h0, l0);
    cvt2(v0.z, v0.w, h1, l1);
    cvt2(v1.x, v1.y, h2, l2);
    cvt2(v1.z, v1.w, h3, l3);
    st128(hi_addr, h0, h1, h2, h3);
    st128(lo_addr, l0, l1, l2, l3);
}

static __device__ __forceinline__ void ldm4(uint32_t d[4], uint32_t addr) {
    asm volatile("ldmatrix.sync.aligned.m8n8.x4.shared.b16 {%0,%1,%2,%3}, [%4];"
                 : "=r"(d[0]), "=r"(d[1]), "=r"(d[2]), "=r"(d[3]) : "r"(addr));
}

static __device__ __forceinline__ uint32_t lds32(uint32_t addr) {
    uint32_t v;
    asm volatile("ld.shared.b32 %0, [%1];" : "=r"(v) : "r"(addr));
    return v;
}

static __device__ __forceinline__ void mma16816(float c[4], const uint32_t a[4],
                                                uint32_t b0, uint32_t b1) {
    asm volatile(
        "mma.sync.aligned.m16n8k16.row.col.f32.bf16.bf16.f32 "
        "{%0,%1,%2,%3}, {%4,%5,%6,%7}, {%8,%9}, {%0,%1,%2,%3};"
        : "+f"(c[0]), "+f"(c[1]), "+f"(c[2]), "+f"(c[3])
        : "r"(a[0]), "r"(a[1]), "r"(a[2]), "r"(a[3]), "r"(b0), "r"(b1));
}

__global__ __launch_bounds__(256, 1)
void gat_mma_kernel(const float* __restrict__ x,
                    const float* __restrict__ W,
                    const float* __restrict__ bias,
                    float* __restrict__ out)
{
    __shared__ __align__(16) unsigned char smem[4 * REGION];  // 40 KB

    const int tid  = threadIdx.x;
    const int lane = tid & 31;
    const int warp = tid >> 5;
    const int wm = (warp >> 2) * 64;   // warp M offset within CTA tile
    const int wn = (warp & 3) * 32;    // warp N offset
    const int m0 = blockIdx.y * BM;
    const int n0 = blockIdx.x * BN;

    const uint32_t AH = smem_u32(smem);
    const uint32_t AL = AH + REGION;
    const uint32_t BH = AH + 2u * REGION;
    const uint32_t BL = AH + 3u * REGION;

    // Loader mapping: each thread owns rows r0 and r0+64 of both tiles,
    // 8 consecutive k-values starting at kq.
    const int r0 = tid >> 2;          // 0..63
    const int kq = (tid & 3) * 8;     // 0,8,16,24

    const float* axA = x + (size_t)(m0 + r0) * IN_C + kq;
    const float* axB = x + (size_t)(m0 + r0 + 64) * IN_C + kq;
    const int jA = n0 + r0, jB = n0 + r0 + 64;
    const float* bxA = W + (size_t)((jA & 7) * 64 + (jA >> 3)) * IN_C + kq;
    const float* bxB = W + (size_t)((jB & 7) * 64 + (jB >> 3)) * IN_C + kq;

    const uint32_t sA1 = (uint32_t)(r0 * PITCH + kq * 2);
    const uint32_t sA2 = sA1 + 64u * PITCH;

    // Prefetch chunk 0 into registers.
    float4 pA0 = *(const float4*)(axA);
    float4 pA1 = *(const float4*)(axA + 4);
    float4 pA2 = *(const float4*)(axB);
    float4 pA3 = *(const float4*)(axB + 4);
    float4 pB0 = *(const float4*)(bxA);
    float4 pB1 = *(const float4*)(bxA + 4);
    float4 pB2 = *(const float4*)(bxB);
    float4 pB3 = *(const float4*)(bxB + 4);

    float acc[4][4][4];
    #pragma unroll
    for (int t = 0; t < 4; t++)
        #pragma unroll
        for (int u = 0; u < 4; u++)
            #pragma unroll
            for (int e = 0; e < 4; e++)
                acc[t][u][e] = 0.f;

    #pragma unroll 1
    for (int c = 0; c < NCHUNK; c++) {
        __syncthreads();   // previous chunk's reads done
        cvt_store8(pA0, pA1, AH + sA1, AL + sA1);
        cvt_store8(pA2, pA3, AH + sA2, AL + sA2);
        cvt_store8(pB0, pB1, BH + sA1, BL + sA1);
        cvt_store8(pB2, pB3, BH + sA2, BL + sA2);
        __syncthreads();   // tiles visible

        if (c + 1 < NCHUNK) {   // prefetch next chunk (hidden under MMA)
            const int o = (c + 1) * KC;
            pA0 = *(const float4*)(axA + o);
            pA1 = *(const float4*)(axA + o + 4);
            pA2 = *(const float4*)(axB + o);
            pA3 = *(const float4*)(axB + o + 4);
            pB0 = *(const float4*)(bxA + o);
            pB1 = *(const float4*)(bxA + o + 4);
            pB2 = *(const float4*)(bxB + o);
            pB3 = *(const float4*)(bxB + o + 4);
        }

        #pragma unroll
        for (int kk = 0; kk < 2; kk++) {
            uint32_t ah[4][4], al[4][4], bh[4][2], bl[4][2];
            #pragma unroll
            for (int t = 0; t < 4; t++) {
                uint32_t off = (uint32_t)((wm + t * 16 + (lane & 15)) * PITCH
                                          + kk * 32 + ((lane >> 4) << 4));
                ldm4(ah[t], AH + off);
                ldm4(al[t], AL + off);
            }
            #pragma unroll
            for (int u = 0; u < 4; u++) {
                uint32_t off = (uint32_t)((wn + u * 8 + (lane >> 2)) * PITCH
                                          + kk * 32 + (lane & 3) * 4);
                bh[u][0] = lds32(BH + off);
                bh[u][1] = lds32(BH + off + 16);
                bl[u][0] = lds32(BL + off);
                bl[u][1] = lds32(BL + off + 16);
            }
            #pragma unroll
            for (int t = 0; t < 4; t++)
                #pragma unroll
                for (int u = 0; u < 4; u++) {
                    mma16816(acc[t][u], ah[t], bh[u][0], bh[u][1]);
                    mma16816(acc[t][u], ah[t], bl[u][0], bl[u][1]);
                    mma16816(acc[t][u], al[t], bh[u][0], bh[u][1]);
                }
        }
    }

    // Epilogue: bias add + store. Fragment mapping of m16n8 accumulators:
    //   c0: (row=lane>>2,      col=(lane&3)*2)   c1: col+1
    //   c2: (row=lane>>2 + 8,  col)              c3: col+1
    #pragma unroll
    for (int u = 0; u < 4; u++) {
        const int col = n0 + wn + u * 8 + (lane & 3) * 2;
        const float2 bv = *(const float2*)(bias + col);
        #pragma unroll
        for (int t = 0; t < 4; t++) {
            const int row = m0 + wm + t * 16 + (lane >> 2);
            float2 o0 = make_float2(acc[t][u][0] + bv.x, acc[t][u][1] + bv.y);
            float2 o1 = make_float2(acc[t][u][2] + bv.x, acc[t][u][3] + bv.y);
            *(float2*)(out + (size_t)row * OUT_TOT + col) = o0;
            *(float2*)(out + (size_t)(row + 8) * OUT_TOT + col) = o1;
        }
    }
}

extern "C" void kernel_launch(void* const* d_in, const int* in_sizes, int n_in,
                              void* d_out, int out_size) {
    // metadata order: adj, x, W, att_src, att_dst, bias
    const float* x    = (const float*)d_in[1];
    const float* W    = (const float*)d_in[2];
    const float* bias = (const float*)d_in[5];
    float* out        = (float*)d_out;

    dim3 grid(OUT_TOT / BN, N_NODES / BM);   // (4, 32) = 128 CTAs, one wave
    gat_mma_kernel<<<grid, 256>>>(x, W, bias, out);
}

// round 4
// speedup vs baseline: 1.8459x; 1.0881x over previous
#include <cuda_runtime.h>
#include <cuda_bf16.h>
#include <cstdint>

// GATConv_74904229642448 — attention collapses to multiply-by-one (row-
// normalized alpha contracted only over its normalization axis):
//   out[n, j] = dot(x[n,:], W[(j&7)*64 + (j>>3), :]) + bias[j]
// => 4096x512x256 fp32 GEMM, adj unused.
//
// Split-bf16 3-term GEMM on mma.sync (tcgen05 not reachable: harness PTX
// target is compute_103). R4: conversion hoisted into a memory-bound
// pre-pass; GEMM stages pre-converted bf16 via cp.async + ldmatrix only.

#define N_NODES 4096
#define IN_C    256
#define OUT_TOT 512
#define BM 128
#define BN 128
#define KC 32
#define NCHUNK (IN_C / KC)        // 8
#define PITCH 80                  // smem row pitch bytes (32 bf16 + 16B pad)
#define REGION (128 * PITCH)      // 10240 B per tile
#define BUFB (4u * REGION)        // Ah, Al, Bh, Bl
#define SMEMB (2u * BUFB)         // 81920 B double-buffered

#define XT (N_NODES * IN_C)
#define WT (OUT_TOT * IN_C)

__device__ __align__(16) __nv_bfloat16 g_xh[XT];
__device__ __align__(16) __nv_bfloat16 g_xl[XT];
__device__ __align__(16) __nv_bfloat16 g_wh[WT];
__device__ __align__(16) __nv_bfloat16 g_wl[WT];

static __device__ __forceinline__ uint32_t smem_u32(const void* p) {
    uint32_t a;
    asm("{ .reg .u64 t; cvta.to.shared.u64 t, %1; cvt.u32.u64 %0, t; }"
        : "=r"(a) : "l"(p));
    return a;
}

static __device__ __forceinline__ uint32_t pack2(__nv_bfloat16 a, __nv_bfloat16 b) {
    return ((uint32_t)__bfloat16_as_ushort(b) << 16) | (uint32_t)__bfloat16_as_ushort(a);
}

// ---------------- pre-pass: fp32 -> (hi, lo) bf16, W permuted ----------------
__global__ __launch_bounds__(256, 8)
void cvt_pre(const float* __restrict__ x, const float* __restrict__ W)
{
    const int i = blockIdx.x * 256 + threadIdx.x;   // one float4 per thread
    const float4* src;
    __nv_bfloat16 *dh, *dl;
    int di;
    if (i < XT / 4) {
        src = (const float4*)x + i;
        dh = g_xh; dl = g_xl; di = i * 4;
    } else {
        const int j = i - XT / 4;                   // < WT/4
        const int row = j >> 6;                     // permuted (output) row
        const int srow = (row & 7) * 64 + (row >> 3);
        src = (const float4*)W + srow * 64 + (j & 63);
        dh = g_wh; dl = g_wl; di = j * 4;
    }
    const float4 v = *src;
    __nv_bfloat16 h0 = __float2bfloat16(v.x);
    __nv_bfloat16 h1 = __float2bfloat16(v.y);
    __nv_bfloat16 h2 = __float2bfloat16(v.z);
    __nv_bfloat16 h3 = __float2bfloat16(v.w);
    __nv_bfloat16 l0 = __float2bfloat16(v.x - __bfloat162float(h0));
    __nv_bfloat16 l1 = __float2bfloat16(v.y - __bfloat162float(h1));
    __nv_bfloat16 l2 = __float2bfloat16(v.z - __bfloat162float(h2));
    __nv_bfloat16 l3 = __float2bfloat16(v.w - __bfloat162float(h3));
    *(uint2*)(dh + di) = make_uint2(pack2(h0, h1), pack2(h2, h3));
    *(uint2*)(dl + di) = make_uint2(pack2(l0, l1), pack2(l2, l3));
}

// ---------------- GEMM ----------------
static __device__ __forceinline__ void cp16(uint32_t dst, const __nv_bfloat16* src) {
    asm volatile("cp.async.cg.shared.global [%0], [%1], 16;"
                 :: "r"(dst), "l"(src) : "memory");
}

static __device__ __forceinline__ void ldm4(uint32_t d[4], uint32_t addr) {
    asm volatile("ldmatrix.sync.aligned.m8n8.x4.shared.b16 {%0,%1,%2,%3}, [%4];"
                 : "=r"(d[0]), "=r"(d[1]), "=r"(d[2]), "=r"(d[3]) : "r"(addr));
}

static __device__ __forceinline__ void mma16816(float c[4], const uint32_t a[4],
                                                uint32_t b0, uint32_t b1) {
    asm volatile(
        "mma.sync.aligned.m16n8k16.row.col.f32.bf16.bf16.f32 "
        "{%0,%1,%2,%3}, {%4,%5,%6,%7}, {%8,%9}, {%0,%1,%2,%3};"
        : "+f"(c[0]), "+f"(c[1]), "+f"(c[2]), "+f"(c[3])
        : "r"(a[0]), "r"(a[1]), "r"(a[2]), "r"(a[3]), "r"(b0), "r"(b1));
}

extern __shared__ __align__(16) unsigned char dynsmem[];

__global__ __launch_bounds__(256, 1)
void gat_mma2(const float* __restrict__ bias, float* __restrict__ out)
{
    const uint32_t S = smem_u32(dynsmem);

    const int tid  = threadIdx.x;
    const int lane = tid & 31;
    const int warp = tid >> 5;
    const int wm = (warp >> 2) * 64;
    const int wn = (warp & 3) * 32;
    const int m0 = blockIdx.y * BM;
    const int n0 = blockIdx.x * BN;

    // cp.async mapping: thread copies rows r0 and r0+64 of each region,
    // one 16B segment (8 bf16) per row.
    const int r0  = tid >> 2;            // 0..63
    const int seg = tid & 3;             // 16B segment
    const __nv_bfloat16* pxh = g_xh + (size_t)(m0 + r0) * IN_C + seg * 8;
    const __nv_bfloat16* pxl = g_xl + (size_t)(m0 + r0) * IN_C + seg * 8;
    const __nv_bfloat16* pwh = g_wh + (size_t)(n0 + r0) * IN_C + seg * 8;
    const __nv_bfloat16* pwl = g_wl + (size_t)(n0 + r0) * IN_C + seg * 8;
    const uint32_t dst0 = (uint32_t)(r0 * PITCH + seg * 16);

    float acc[4][4][4];
    #pragma unroll
    for (int t = 0; t < 4; t++)
        #pragma unroll
        for (int u = 0; u < 4; u++)
            #pragma unroll
            for (int e = 0; e < 4; e++)
                acc[t][u][e] = 0.f;

    // issue chunk c's copies into buffer c&1
    auto issue = [&](int c) {
        const uint32_t D = S + (uint32_t)(c & 1) * BUFB + dst0;
        const int go = c * KC;
        cp16(D,                            pxh + go);
        cp16(D + 64u * PITCH,              pxh + go + 64 * IN_C);
        cp16(D + REGION,                   pxl + go);
        cp16(D + REGION + 64u * PITCH,     pxl + go + 64 * IN_C);
        cp16(D + 2u * REGION,              pwh + go);
        cp16(D + 2u * REGION + 64u * PITCH, pwh + go + 64 * IN_C);
        cp16(D + 3u * REGION,              pwl + go);
        cp16(D + 3u * REGION + 64u * PITCH, pwl + go + 64 * IN_C);
        asm volatile("cp.async.commit_group;" ::: "memory");
    };

    issue(0);

    #pragma unroll 1
    for (int c = 0; c < NCHUNK; c++) {
        asm volatile("cp.async.wait_group 0;" ::: "memory");
        __syncthreads();
        if (c + 1 < NCHUNK) issue(c + 1);

        const uint32_t AH = S + (uint32_t)(c & 1) * BUFB;
        const uint32_t AL = AH + REGION;
        const uint32_t BH = AH + 2u * REGION;
        const uint32_t BL = AH + 3u * REGION;

        #pragma unroll
        for (int kk = 0; kk < 2; kk++) {
            uint32_t ah[4][4], al[4][4], bh[2][4], bl[2][4];
            #pragma unroll
            for (int t = 0; t < 4; t++) {
                uint32_t off = (uint32_t)((wm + t * 16 + (lane & 15)) * PITCH
                                          + kk * 32 + ((lane >> 4) << 4));
                ldm4(ah[t], AH + off);
                ldm4(al[t], AL + off);
            }
            #pragma unroll
            for (int u2 = 0; u2 < 2; u2++) {
                // lanes 0-7: rows u=2*u2, k lo | 8-15: k hi | 16-23: u=2*u2+1 k lo | 24-31: k hi
                uint32_t off = (uint32_t)((wn + u2 * 16 + ((lane >> 4) << 3) + (lane & 7)) * PITCH
                                          + kk * 32 + ((lane >> 3) & 1) * 16);
                ldm4(bh[u2], BH + off);
                ldm4(bl[u2], BL + off);
            }
            #pragma unroll
            for (int t = 0; t < 4; t++)
                #pragma unroll
                for (int u = 0; u < 4; u++) {
                    const int u2 = u >> 1, e = (u & 1) * 2;
                    mma16816(acc[t][u], ah[t], bh[u2][e], bh[u2][e + 1]);
                    mma16816(acc[t][u], ah[t], bl[u2][e], bl[u2][e + 1]);
                    mma16816(acc[t][u], al[t], bh[u2][e], bh[u2][e + 1]);
                }
        }
    }

    // Epilogue: bias + store. m16n8 acc mapping:
    //   c0:(row=lane>>2, col=(lane&3)*2) c1:col+1 c2:row+8 c3:row+8,col+1
    #pragma unroll
    for (int u = 0; u < 4; u++) {
        const int col = n0 + wn + u * 8 + (lane & 3) * 2;
        const float2 bv = *(const float2*)(bias + col);
        #pragma unroll
        for (int t = 0; t < 4; t++) {
            const int row = m0 + wm + t * 16 + (lane >> 2);
            float2 o0 = make_float2(acc[t][u][0] + bv.x, acc[t][u][1] + bv.y);
            float2 o1 = make_float2(acc[t][u][2] + bv.x, acc[t][u][3] + bv.y);
            *(float2*)(out + (size_t)row * OUT_TOT + col) = o0;
            *(float2*)(out + (size_t)(row + 8) * OUT_TOT + col) = o1;
        }
    }
}

extern "C" void kernel_launch(void* const* d_in, const int* in_sizes, int n_in,
                              void* d_out, int out_size) {
    // metadata order: adj, x, W, att_src, att_dst, bias
    const float* x    = (const float*)d_in[1];
    const float* W    = (const float*)d_in[2];
    const float* bias = (const float*)d_in[5];
    float* out        = (float*)d_out;

    cudaFuncSetAttribute(gat_mma2, cudaFuncAttributeMaxDynamicSharedMemorySize,
                         (int)SMEMB);

    const int pre_blocks = (XT / 4 + WT / 4) / 256;      // 1152
    cvt_pre<<<pre_blocks, 256>>>(x, W);

    dim3 grid(OUT_TOT / BN, N_NODES / BM);               // (4, 32) = 128 CTAs
    gat_mma2<<<grid, 256, SMEMB>>>(bias, out);
}

// round 6
// speedup vs baseline: 1.9599x; 1.0618x over previous
#include <cuda_runtime.h>
#include <cuda_bf16.h>
#include <cstdint>

// GATConv_74904229642448 — attention collapses to multiply-by-one (row-
// normalized alpha contracted only over its normalization axis):
//   out[n, j] = dot(x[n,:], W[(j&7)*64 + (j>>3), :]) + bias[j]
// => 4096x512x256 fp32 GEMM, adj unused.
//
// Split-bf16 3-term GEMM on mma.sync (tcgen05 unreachable: harness PTX
// target is compute_103). R5: 512 threads/CTA (16 warps, 4/SMSP) for
// latency hiding; warp tile 32x32; conversion stays in a pre-pass.

#define N_NODES 4096
#define IN_C    256
#define OUT_TOT 512
#define BM 128
#define BN 128
#define KC 32
#define NCHUNK (IN_C / KC)        // 8
#define PITCH 80                  // smem row pitch bytes (32 bf16 + 16B pad)
#define REGION (128 * PITCH)      // 10240 B per tile
#define BUFB (4u * REGION)        // Ah, Al, Bh, Bl
#define SMEMB (2u * BUFB)         // 81920 B double-buffered

#define XT (N_NODES * IN_C)
#define WT (OUT_TOT * IN_C)

__device__ __align__(16) __nv_bfloat16 g_xh[XT];
__device__ __align__(16) __nv_bfloat16 g_xl[XT];
__device__ __align__(16) __nv_bfloat16 g_wh[WT];
__device__ __align__(16) __nv_bfloat16 g_wl[WT];

static __device__ __forceinline__ uint32_t smem_u32(const void* p) {
    uint32_t a;
    asm("{ .reg .u64 t; cvta.to.shared.u64 t, %1; cvt.u32.u64 %0, t; }"
        : "=r"(a) : "l"(p));
    return a;
}

static __device__ __forceinline__ uint32_t pack2(__nv_bfloat16 a, __nv_bfloat16 b) {
    return ((uint32_t)__bfloat16_as_ushort(b) << 16) | (uint32_t)__bfloat16_as_ushort(a);
}

// ---------------- pre-pass: fp32 -> (hi, lo) bf16, W permuted ----------------
__global__ __launch_bounds__(256, 8)
void cvt_pre(const float* __restrict__ x, const float* __restrict__ W)
{
    const int i = blockIdx.x * 256 + threadIdx.x;   // one float4 per thread
    const float4* src;
    __nv_bfloat16 *dh, *dl;
    int di;
    if (i < XT / 4) {
        src = (const float4*)x + i;
        dh = g_xh; dl = g_xl; di = i * 4;
    } else {
        const int j = i - XT / 4;                   // < WT/4
        const int row = j >> 6;                     // permuted (output) row
        const int srow = (row & 7) * 64 + (row >> 3);
        src = (const float4*)W + srow * 64 + (j & 63);
        dh = g_wh; dl = g_wl; di = j * 4;
    }
    const float4 v = *src;
    __nv_bfloat16 h0 = __float2bfloat16(v.x);
    __nv_bfloat16 h1 = __float2bfloat16(v.y);
    __nv_bfloat16 h2 = __float2bfloat16(v.z);
    __nv_bfloat16 h3 = __float2bfloat16(v.w);
    __nv_bfloat16 l0 = __float2bfloat16(v.x - __bfloat162float(h0));
    __nv_bfloat16 l1 = __float2bfloat16(v.y - __bfloat162float(h1));
    __nv_bfloat16 l2 = __float2bfloat16(v.z - __bfloat162float(h2));
    __nv_bfloat16 l3 = __float2bfloat16(v.w - __bfloat162float(h3));
    *(uint2*)(dh + di) = make_uint2(pack2(h0, h1), pack2(h2, h3));
    *(uint2*)(dl + di) = make_uint2(pack2(l0, l1), pack2(l2, l3));
}

// ---------------- GEMM ----------------
static __device__ __forceinline__ void cp16(uint32_t dst, const __nv_bfloat16* src) {
    asm volatile("cp.async.cg.shared.global [%0], [%1], 16;"
                 :: "r"(dst), "l"(src) : "memory");
}

static __device__ __forceinline__ void ldm4(uint32_t d[4], uint32_t addr) {
    asm volatile("ldmatrix.sync.aligned.m8n8.x4.shared.b16 {%0,%1,%2,%3}, [%4];"
                 : "=r"(d[0]), "=r"(d[1]), "=r"(d[2]), "=r"(d[3]) : "r"(addr));
}

static __device__ __forceinline__ void mma16816(float c[4], const uint32_t a[4],
                                                uint32_t b0, uint32_t b1) {
    asm volatile(
        "mma.sync.aligned.m16n8k16.row.col.f32.bf16.bf16.f32 "
        "{%0,%1,%2,%3}, {%4,%5,%6,%7}, {%8,%9}, {%0,%1,%2,%3};"
        : "+f"(c[0]), "+f"(c[1]), "+f"(c[2]), "+f"(c[3])
        : "r"(a[0]), "r"(a[1]), "r"(a[2]), "r"(a[3]), "r"(b0), "r"(b1));
}

extern __shared__ __align__(16) unsigned char dynsmem[];

__global__ __launch_bounds__(512, 1)
void gat_mma3(const float* __restrict__ bias, float* __restrict__ out)
{
    const uint32_t S = smem_u32(dynsmem);

    const int tid  = threadIdx.x;
    const int lane = tid & 31;
    const int warp = tid >> 5;          // 0..15
    const int wm = (warp >> 2) * 32;    // 4 warp-rows of 32
    const int wn = (warp & 3) * 32;     // 4 warp-cols of 32
    const int m0 = blockIdx.y * BM;
    const int n0 = blockIdx.x * BN;

    // cp.async mapping: each thread owns one (row, 16B-seg) of every region.
    const int r   = tid >> 2;            // 0..127
    const int seg = tid & 3;
    const __nv_bfloat16* pxh = g_xh + (size_t)(m0 + r) * IN_C + seg * 8;
    const __nv_bfloat16* pxl = g_xl + (size_t)(m0 + r) * IN_C + seg * 8;
    const __nv_bfloat16* pwh = g_wh + (size_t)(n0 + r) * IN_C + seg * 8;
    const __nv_bfloat16* pwl = g_wl + (size_t)(n0 + r) * IN_C + seg * 8;
    const uint32_t dst0 = (uint32_t)(r * PITCH + seg * 16);

    float acc[2][4][4];
    #pragma unroll
    for (int t = 0; t < 2; t++)
        #pragma unroll
        for (int u = 0; u < 4; u++)
            #pragma unroll
            for (int e = 0; e < 4; e++)
                acc[t][u][e] = 0.f;

    auto issue = [&](int c) {
        const uint32_t D = S + (uint32_t)(c & 1) * BUFB + dst0;
        const int go = c * KC;
        cp16(D,                pxh + go);
        cp16(D + REGION,       pxl + go);
        cp16(D + 2u * REGION,  pwh + go);
        cp16(D + 3u * REGION,  pwl + go);
        asm volatile("cp.async.commit_group;" ::: "memory");
    };

    issue(0);

    #pragma unroll 1
    for (int c = 0; c < NCHUNK; c++) {
        asm volatile("cp.async.wait_group 0;" ::: "memory");
        __syncthreads();
        if (c + 1 < NCHUNK) issue(c + 1);

        const uint32_t AH = S + (uint32_t)(c & 1) * BUFB;
        const uint32_t AL = AH + REGION;
        const uint32_t BH = AH + 2u * REGION;
        const uint32_t BL = AH + 3u * REGION;

        #pragma unroll
        for (int kk = 0; kk < 2; kk++) {
            uint32_t ah[2][4], al[2][4], bh[2][4], bl[2][4];
            #pragma unroll
            for (int t = 0; t < 2; t++) {
                uint32_t off = (uint32_t)((wm + t * 16 + (lane & 15)) * PITCH
                                          + kk * 32 + ((lane >> 4) << 4));
                ldm4(ah[t], AH + off);
                ldm4(al[t], AL + off);
            }
            #pragma unroll
            for (int u2 = 0; u2 < 2; u2++) {
                // lanes 0-7: first 8 rows, k lo | 8-15: k hi | 16-23: next 8 rows | 24-31: hi
                uint32_t off = (uint32_t)((wn + u2 * 16 + ((lane >> 4) << 3) + (lane & 7)) * PITCH
                                          + kk * 32 + ((lane >> 3) & 1) * 16);
                ldm4(bh[u2], BH + off);
                ldm4(bl[u2], BL + off);
            }
            #pragma unroll
            for (int t = 0; t < 2; t++)
                #pragma unroll
                for (int u = 0; u < 4; u++) {
                    const int u2 = u >> 1, e = (u & 1) * 2;
                    mma16816(acc[t][u], ah[t], bh[u2][e], bh[u2][e + 1]);
                    mma16816(acc[t][u], ah[t], bl[u2][e], bl[u2][e + 1]);
                    mma16816(acc[t][u], al[t], bh[u2][e], bh[u2][e + 1]);
                }
        }
    }

    // Epilogue: bias + store. m16n8 acc mapping:
    //   c0:(row=lane>>2, col=(lane&3)*2) c1:col+1 c2:row+8 c3:row+8,col+1
    #pragma unroll
    for (int u = 0; u < 4; u++) {
        const int col = n0 + wn + u * 8 + (lane & 3) * 2;
        const float2 bv = *(const float2*)(bias + col);
        #pragma unroll
        for (int t = 0; t < 2; t++) {
            const int row = m0 + wm + t * 16 + (lane >> 2);
            float2 o0 = make_float2(acc[t][u][0] + bv.x, acc[t][u][1] + bv.y);
            float2 o1 = make_float2(acc[t][u][2] + bv.x, acc[t][u][3] + bv.y);
            *(float2*)(out + (size_t)row * OUT_TOT + col) = o0;
            *(float2*)(out + (size_t)(row + 8) * OUT_TOT + col) = o1;
        }
    }
}

extern "C" void kernel_launch(void* const* d_in, const int* in_sizes, int n_in,
                              void* d_out, int out_size) {
    // metadata order: adj, x, W, att_src, att_dst, bias
    const float* x    = (const float*)d_in[1];
    const float* W    = (const float*)d_in[2];
    const float* bias = (const float*)d_in[5];
    float* out        = (float*)d_out;

    cudaFuncSetAttribute(gat_mma3, cudaFuncAttributeMaxDynamicSharedMemorySize,
                         (int)SMEMB);

    const int pre_blocks = (XT / 4 + WT / 4) / 256;      // 1152
    cvt_pre<<<pre_blocks, 256>>>(x, W);

    dim3 grid(OUT_TOT / BN, N_NODES / BM);               // (4, 32) = 128 CTAs
    gat_mma3<<<grid, 512, SMEMB>>>(bias, out);
}